// round 7
// baseline (speedup 1.0000x reference)
#include <cuda_runtime.h>
#include <math.h>
#include <stdint.h>

// Problem constants
#define S_LEN   2048
#define D_MODEL 1024
#define NHEAD   16
#define HDIM    64
#define BATCH   4
#define BH      (BATCH * NHEAD)   // 64

// Scratch (device globals — no allocation allowed)
__device__ float g_q[(size_t)BH * S_LEN * HDIM];          // [B,H,S,hd] rope'd, pre-scaled, tf32
__device__ float g_k[(size_t)BH * S_LEN * HDIM];          // [B,H,S,hd]
__device__ float g_v[(size_t)BH * HDIM * S_LEN];          // [B,H,hd,S]  TRANSPOSED
__device__ float g_attn[(size_t)BATCH * S_LEN * D_MODEL]; // [B,S,D], tf32-rounded
__device__ float g_cos[S_LEN * (HDIM / 2)];
__device__ float g_sin[S_LEN * (HDIM / 2)];
__device__ float g_xc[(size_t)BATCH * S_LEN * D_MODEL];   // tf32-rounded x
__device__ float g_wc[(size_t)3 * D_MODEL * D_MODEL];     // tf32-rounded w_qkv
__device__ float g_woc[(size_t)D_MODEL * D_MODEL];        // tf32-rounded w_o
__device__ float g_bias[BATCH * S_LEN];                   // 0 or -1e30 padding bias

// ---------------------------------------------------------------------------
// helpers
// ---------------------------------------------------------------------------
__device__ __forceinline__ float to_tf32(float x) {
    float r;
    asm("cvt.rna.tf32.f32 %0, %1;" : "=f"(r) : "f"(x));
    return r;
}

__device__ __forceinline__ void mma_m16n8k8(
    float* c, float a0, float a1, float a2, float a3, float b0, float b1)
{
    uint32_t ua0 = __float_as_uint(a0), ua1 = __float_as_uint(a1);
    uint32_t ua2 = __float_as_uint(a2), ua3 = __float_as_uint(a3);
    uint32_t ub0 = __float_as_uint(b0), ub1 = __float_as_uint(b1);
    asm volatile(
        "mma.sync.aligned.m16n8k8.row.col.f32.tf32.tf32.f32 "
        "{%0,%1,%2,%3}, {%4,%5,%6,%7}, {%8,%9}, {%0,%1,%2,%3};"
        : "+f"(c[0]), "+f"(c[1]), "+f"(c[2]), "+f"(c[3])
        : "r"(ua0), "r"(ua1), "r"(ua2), "r"(ua3), "r"(ub0), "r"(ub1));
}

__device__ __forceinline__ uint32_t smem_u32(const void* p) {
    return (uint32_t)__cvta_generic_to_shared(p);
}
#define CP16(d, s)  asm volatile("cp.async.ca.shared.global [%0], [%1], 16;" :: "r"(d), "l"(s))
#define CP_COMMIT   asm volatile("cp.async.commit_group;")
#define CP_WAIT0    asm volatile("cp.async.wait_group 0;")
#define CP_WAIT1    asm volatile("cp.async.wait_group 1;")

// ---------------------------------------------------------------------------
// prep kernels
// ---------------------------------------------------------------------------
__global__ void rope_table_kernel() {
    int idx = blockIdx.x * blockDim.x + threadIdx.x;
    if (idx >= S_LEN * (HDIM / 2)) return;
    int s = idx >> 5;
    int i = idx & 31;
    float inv = exp2f(-13.287712379549449f * (2.0f * (float)i / 64.0f));
    float ang = (float)s * inv;
    float sn, cs;
    sincosf(ang, &sn, &cs);
    g_cos[idx] = cs;
    g_sin[idx] = sn;
}

#define N4_X  2097152
#define N4_W  786432
#define N4_WO 262144
__global__ void cvt_all_kernel(const float4* __restrict__ x,
                               const float4* __restrict__ w,
                               const float4* __restrict__ wo) {
    int i = blockIdx.x * blockDim.x + threadIdx.x;
    const float4* src;
    float4* dst;
    if (i < N4_X)                    { src = x + i;                 dst = (float4*)g_xc + i; }
    else if (i < N4_X + N4_W)        { src = w + (i - N4_X);        dst = (float4*)g_wc + (i - N4_X); }
    else if (i < N4_X + N4_W + N4_WO){ src = wo + (i - N4_X - N4_W);dst = (float4*)g_woc + (i - N4_X - N4_W); }
    else return;
    float4 v = *src;
    *dst = make_float4(to_tf32(v.x), to_tf32(v.y), to_tf32(v.z), to_tf32(v.w));
}

__global__ void bias_kernel(const int* __restrict__ pmask) {
    int i = blockIdx.x * blockDim.x + threadIdx.x;
    if (i < BATCH * S_LEN)
        g_bias[i] = (pmask[i] == 0) ? -1e30f : 0.0f;
}

// ---------------------------------------------------------------------------
// tf32 tensor-core GEMM: C[m,n] = sum_k A[m,k] * Bw[n,k]   (K = 1024)
// BK=32, 3-stage cp.async ring, ONE barrier per tile, XOR-swizzled smem
// (stride 32 floats, 16B-chunk index ^= row&7), LDS.128 fragment loads
// feeding 2 MMAs each (4-wide k-permutation on both operands).
// MODE 0: qkv projection -> RoPE + 0.125 q-scale + head-scatter (V transposed)
// MODE 1: plain fp32 store to Out
// ---------------------------------------------------------------------------
#define MM_STAGE_FLOATS (128 * 32)              // 4096 floats = 16KB per operand stage
#define MM_SM_BYTES     (6 * MM_STAGE_FLOATS * 4)  // 3 stages x (A+B) = 98304B

__device__ __forceinline__ void mm_stage(
    float* sA, float* sB, const float* Ag, const float* Bg, int tid)
{
    const int row0 = tid >> 3;        // 0..31
    const int ch   = tid & 7;         // 16B chunk 0..7
#pragma unroll
    for (int i = 0; i < 4; ++i) {
        int r  = row0 + i * 32;
        int sw = ((ch ^ (r & 7)) << 2);
        CP16(smem_u32(sA + r * 32 + sw), Ag + (size_t)r * 1024 + ch * 4);
        CP16(smem_u32(sB + r * 32 + sw), Bg + (size_t)r * 1024 + ch * 4);
    }
}

template<int MODE>
__global__ __launch_bounds__(256, 2) void mm_tf32(
    const float* __restrict__ A, const float* __restrict__ Bw,
    float* __restrict__ Out)
{
    extern __shared__ float smbuf[];
    // stage s: A at smbuf + s*4096, B at smbuf + 12288 + s*4096

    const int tid    = threadIdx.x;
    const int m_base = blockIdx.y * 128;
    const int n_base = blockIdx.x * 128;

    const float* Ag = A  + (size_t)m_base * 1024;
    const float* Bg = Bw + (size_t)n_base * 1024;

    const int warp = tid >> 5;
    const int lane = tid & 31;
    const int wm = warp & 1;
    const int wn = warp >> 1;
    const int g  = lane >> 2;
    const int tg = lane & 3;

    float acc[4][4][4];
#pragma unroll
    for (int mi = 0; mi < 4; mi++)
#pragma unroll
        for (int ni = 0; ni < 4; ni++)
#pragma unroll
            for (int j = 0; j < 4; j++) acc[mi][ni][j] = 0.0f;

    // prologue: stage tiles 0, 1
#pragma unroll
    for (int p = 0; p < 2; ++p) {
        mm_stage(smbuf + p * MM_STAGE_FLOATS,
                 smbuf + 3 * MM_STAGE_FLOATS + p * MM_STAGE_FLOATS,
                 Ag + p * 32, Bg + p * 32, tid);
        CP_COMMIT;
    }

    int sidx = 0;
    for (int kt = 0; kt < 32; ++kt) {
        CP_WAIT1;          // tile kt complete
        __syncthreads();   // visibility + readers of tile kt-1 done

        {   // prefetch tile kt+2 into stage (sidx+2)%3 (= stage of tile kt-1)
            int ps = sidx + 2; if (ps >= 3) ps -= 3;
            if (kt + 2 < 32)
                mm_stage(smbuf + ps * MM_STAGE_FLOATS,
                         smbuf + 3 * MM_STAGE_FLOATS + ps * MM_STAGE_FLOATS,
                         Ag + (kt + 2) * 32, Bg + (kt + 2) * 32, tid);
            CP_COMMIT;
        }

        const float* Asb = smbuf + sidx * MM_STAGE_FLOATS;
        const float* Bsb = smbuf + 3 * MM_STAGE_FLOATS + sidx * MM_STAGE_FLOATS;
#pragma unroll
        for (int j = 0; j < 2; ++j) {           // each j = 2 MMAs (k16)
            const int sw = (((tg + 4 * j) ^ g) << 2);
            float4 af[4][2], bf[4];
#pragma unroll
            for (int mi = 0; mi < 4; mi++) {
                int r = wm * 64 + mi * 16 + g;
                af[mi][0] = *(const float4*)&Asb[r * 32 + sw];
                af[mi][1] = *(const float4*)&Asb[(r + 8) * 32 + sw];
            }
#pragma unroll
            for (int ni = 0; ni < 4; ni++) {
                int cN = wn * 32 + ni * 8 + g;
                bf[ni] = *(const float4*)&Bsb[cN * 32 + sw];
            }
#pragma unroll
            for (int mi = 0; mi < 4; mi++)
#pragma unroll
                for (int ni = 0; ni < 4; ni++) {
                    mma_m16n8k8(acc[mi][ni],
                                af[mi][0].x, af[mi][1].x,
                                af[mi][0].y, af[mi][1].y,
                                bf[ni].x, bf[ni].y);
                    mma_m16n8k8(acc[mi][ni],
                                af[mi][0].z, af[mi][1].z,
                                af[mi][0].w, af[mi][1].w,
                                bf[ni].z, bf[ni].w);
                }
        }
        if (++sidx == 3) sidx = 0;
    }

#pragma unroll
    for (int mi = 0; mi < 4; mi++) {
        int row0 = m_base + wm * 64 + mi * 16 + g;
#pragma unroll
        for (int ni = 0; ni < 4; ni++) {
            int coln = n_base + wn * 32 + ni * 8 + 2 * tg;
            if (MODE == 0) {
                int part = coln >> 10;
                int cc   = coln & 1023;
                int h    = cc >> 6;
                int d0   = cc & 63;
                int i0   = d0 >> 1;
#pragma unroll
                for (int half = 0; half < 2; half++) {
                    int m = row0 + half * 8;
                    int b = m >> 11, s = m & 2047;
                    float v0 = acc[mi][ni][half * 2 + 0];
                    float v1 = acc[mi][ni][half * 2 + 1];
                    if (part == 2) {
                        // V: transposed store [B,H,d,S]
                        size_t base = ((size_t)(b * NHEAD + h) * HDIM + d0) * S_LEN + s;
                        g_v[base]         = to_tf32(v0);
                        g_v[base + S_LEN] = to_tf32(v1);
                    } else {
                        float cs = g_cos[s * 32 + i0], sn = g_sin[s * 32 + i0];
                        float r0 = v0 * cs - v1 * sn;
                        float r1 = v0 * sn + v1 * cs;
                        if (part == 0) { r0 *= 0.125f; r1 *= 0.125f; }
                        float* dst = (part == 0) ? g_q : g_k;
                        *(float2*)(dst + (((size_t)(b * NHEAD + h) * S_LEN + s) * HDIM + d0))
                            = make_float2(to_tf32(r0), to_tf32(r1));
                    }
                }
            } else {
#pragma unroll
                for (int half = 0; half < 2; half++) {
                    int m = row0 + half * 8;
                    *(float2*)(Out + (size_t)m * 1024 + coln)
                        = make_float2(acc[mi][ni][half * 2 + 0],
                                      acc[mi][ni][half * 2 + 1]);
                }
            }
        }
    }
}

// ---------------------------------------------------------------------------
// Tensor-core flash attention (tf32 mma.sync).
// q-tile 128 rows, k-tile 64 keys, 2-stage cp.async, ONE barrier per k-tile.
// Q/K smem XOR-swizzled (stride 64, chunk ^= row&7) for LDS.128 frag loads.
// V is TRANSPOSED in gmem [B,H,d,S]; V tile smem [d][keys] stride 72 ->
// conflict-free float2 PV B-fragments.
// ---------------------------------------------------------------------------
// Smem floats: Qs 128*64, Ks 2*64*64, Vs 2*64*72, PM 2*64
#define ATTN_SM_FLOATS (8192 + 8192 + 9216 + 128)
#define ATTN_SM_BYTES  (ATTN_SM_FLOATS * 4)

__device__ __forceinline__ void stage_kv(
    float* Kdst, float* Vdst, float* PMdst,
    const float* Kg_tile, const float* Vg_col, const float* Bsrc, int tid)
{
#pragma unroll
    for (int i = 0; i < 4; ++i) {
        int idx = tid + i * 256;
        int row = idx >> 4;          // K: key row 0..63 ; V: d row 0..63
        int ch  = idx & 15;          // 16B chunk 0..15
        CP16(smem_u32(Kdst + row * 64 + ((ch ^ (row & 7)) << 2)),
             Kg_tile + (size_t)row * 64 + ch * 4);
        CP16(smem_u32(Vdst + row * 72 + ch * 4),
             Vg_col + (size_t)row * S_LEN + ch * 4);
    }
    if (tid < 16) CP16(smem_u32(PMdst + tid * 4), Bsrc + tid * 4);
}

__global__ __launch_bounds__(256, 2) void attn_tc()
{
    extern __shared__ float sm[];
    float* Qs = sm;                 // [128][64] swizzled
    float* Ks = Qs + 8192;          // [2][64][64] swizzled
    float* Vs = Ks + 8192;          // [2][64][72]  (rows = d)
    float* PM = Vs + 9216;          // [2][64]

    const int qt    = 15 - (int)blockIdx.x;         // heavy tiles first
    const int qbase = qt * 128;
    const int bh = blockIdx.y;
    const int b  = bh >> 4, h = bh & 15;
    const int tid  = threadIdx.x;
    const int warp = tid >> 5, lane = tid & 31;
    const int g = lane >> 2, tg = lane & 3;
    const int nkt = 2 * (qt + 1);

    const float* Kg = g_k + (size_t)bh * S_LEN * HDIM;
    const float* Vg = g_v + (size_t)bh * HDIM * S_LEN;   // [d][s]
    const float* Bg = g_bias + b * S_LEN;

    // prefetch k-tile 0
    stage_kv(Ks, Vs, PM, Kg, Vg, Bg, tid);
    CP_COMMIT;

    // stage Q tile [128][64] -> swizzled
    {
        const float* Qg = g_q + ((size_t)bh * S_LEN + qbase) * HDIM;
#pragma unroll
        for (int r = 0; r < 8; ++r) {
            int idx = tid + r * 256;
            int row = idx >> 4, ch = idx & 15;
            *(float4*)&Qs[row * 64 + ((ch ^ (row & 7)) << 2)]
                = *(const float4*)&Qg[row * 64 + ch * 4];
        }
    }

    float S[8][4], O[8][4], mrow[2], lrow[2];
    mrow[0] = mrow[1] = -INFINITY;
    lrow[0] = lrow[1] = 0.0f;
#pragma unroll
    for (int t = 0; t < 8; t++)
#pragma unroll
        for (int j = 0; j < 4; j++) O[t][j] = 0.0f;

    const int wrow0 = qbase + warp * 16;

    for (int kt = 0; kt < nkt; ++kt) {
        const int buf   = kt & 1;
        const int kbase = kt * 64;

        CP_WAIT0;
        __syncthreads();

        if (kt + 1 < nkt) {
            int nb  = buf ^ 1;
            int kb2 = (kt + 1) * 64;
            stage_kv(Ks + nb * 4096, Vs + nb * 4608, PM + nb * 64,
                     Kg + (size_t)kb2 * 64, Vg + kb2, Bg + kb2, tid);
        }
        CP_COMMIT;

        if (kbase <= wrow0 + 15) {     // per-warp causal tile skip
            const float* Kb  = Ks + buf * 4096;
            const float* Vb  = Vs + buf * 4608;
            const float* PMb = PM + buf * 64;

            // ---- S = Q K^T  (q pre-scaled by 1/8)
#pragma unroll
            for (int nt = 0; nt < 8; nt++)
#pragma unroll
                for (int j = 0; j < 4; j++) S[nt][j] = 0.0f;

            const int qrow = (warp * 16 + g) * 64;
#pragma unroll
            for (int j = 0; j < 4; ++j) {       // 4 pairs = 8 MMAs over d=64
                const int sw = (((tg + 4 * j) ^ g) << 2);
                float4 a0 = *(const float4*)&Qs[qrow + sw];
                float4 a1 = *(const float4*)&Qs[qrow + 8 * 64 + sw];
#pragma unroll
                for (int nt = 0; nt < 8; ++nt) {
                    float4 kb = *(const float4*)&Kb[(nt * 8 + g) * 64 + sw];
                    mma_m16n8k8(S[nt], a0.x, a1.x, a0.y, a1.y, kb.x, kb.y);
                    mma_m16n8k8(S[nt], a0.z, a1.z, a0.w, a1.w, kb.z, kb.w);
                }
            }

            // ---- mask + online softmax
            float2 pmb[8];
#pragma unroll
            for (int nt = 0; nt < 8; nt++)
                pmb[nt] = *(const float2*)&PMb[nt * 8 + 2 * tg];

            const bool do_causal = (kbase + 63 > wrow0);

            {
                int row_lo = wrow0 + g;
                int row_hi = row_lo + 8;
                float mx_lo = -INFINITY, mx_hi = -INFINITY;
#pragma unroll
                for (int nt = 0; nt < 8; nt++) {
                    int col0 = kbase + nt * 8 + 2 * tg;
                    float v0 = S[nt][0] + pmb[nt].x;
                    float v1 = S[nt][1] + pmb[nt].y;
                    float v2 = S[nt][2] + pmb[nt].x;
                    float v3 = S[nt][3] + pmb[nt].y;
                    if (do_causal) {
                        if (col0     > row_lo) v0 = -1e30f;
                        if (col0 + 1 > row_lo) v1 = -1e30f;
                        if (col0     > row_hi) v2 = -1e30f;
                        if (col0 + 1 > row_hi) v3 = -1e30f;
                    }
                    S[nt][0] = v0; S[nt][1] = v1;
                    S[nt][2] = v2; S[nt][3] = v3;
                    mx_lo = fmaxf(mx_lo, fmaxf(v0, v1));
                    mx_hi = fmaxf(mx_hi, fmaxf(v2, v3));
                }
                mx_lo = fmaxf(mx_lo, __shfl_xor_sync(0xffffffffu, mx_lo, 1));
                mx_lo = fmaxf(mx_lo, __shfl_xor_sync(0xffffffffu, mx_lo, 2));
                mx_hi = fmaxf(mx_hi, __shfl_xor_sync(0xffffffffu, mx_hi, 1));
                mx_hi = fmaxf(mx_hi, __shfl_xor_sync(0xffffffffu, mx_hi, 2));

                float mn_lo = fmaxf(mrow[0], mx_lo);
                float mn_hi = fmaxf(mrow[1], mx_hi);
                float al_lo = __expf(mrow[0] - mn_lo);
                float al_hi = __expf(mrow[1] - mn_hi);

                float s_lo = 0.0f, s_hi = 0.0f;
#pragma unroll
                for (int nt = 0; nt < 8; nt++) {
                    float p0 = __expf(S[nt][0] - mn_lo);
                    float p1 = __expf(S[nt][1] - mn_lo);
                    float p2 = __expf(S[nt][2] - mn_hi);
                    float p3 = __expf(S[nt][3] - mn_hi);
                    s_lo += p0 + p1;
                    s_hi += p2 + p3;
                    S[nt][0] = to_tf32(p0);
                    S[nt][1] = to_tf32(p1);
                    S[nt][2] = to_tf32(p2);
                    S[nt][3] = to_tf32(p3);
                }
                s_lo += __shfl_xor_sync(0xffffffffu, s_lo, 1);
                s_lo += __shfl_xor_sync(0xffffffffu, s_lo, 2);
                s_hi += __shfl_xor_sync(0xffffffffu, s_hi, 1);
                s_hi += __shfl_xor_sync(0xffffffffu, s_hi, 2);

                lrow[0] = lrow[0] * al_lo + s_lo;
                lrow[1] = lrow[1] * al_hi + s_hi;
                mrow[0] = mn_lo;
                mrow[1] = mn_hi;
#pragma unroll
                for (int hd = 0; hd < 8; hd++) {
                    O[hd][0] *= al_lo;
                    O[hd][1] *= al_lo;
                    O[hd][2] *= al_hi;
                    O[hd][3] *= al_hi;
                }
            }

            // ---- O += P V   (B from transposed V tile: float2, conflict-free)
#pragma unroll
            for (int ks = 0; ks < 8; ++ks) {
#pragma unroll
                for (int hd = 0; hd < 8; ++hd) {
                    float2 bv = *(const float2*)&Vb[(hd * 8 + g) * 72 + ks * 8 + 2 * tg];
                    mma_m16n8k8(O[hd], S[ks][0], S[ks][2],
                                       S[ks][1], S[ks][3], bv.x, bv.y);
                }
            }
        }
    }

    // epilogue: normalize + write g_attn (tf32-rounded for the out-proj GEMM)
    {
        float inv_lo = 1.0f / lrow[0];
        float inv_hi = 1.0f / lrow[1];
        int row_lo = wrow0 + g;
#pragma unroll
        for (int hd = 0; hd < 8; hd++) {
            int col = h * 64 + hd * 8 + 2 * tg;
            *(float2*)(g_attn + ((size_t)b * S_LEN + row_lo) * D_MODEL + col) =
                make_float2(to_tf32(O[hd][0] * inv_lo),
                            to_tf32(O[hd][1] * inv_lo));
            *(float2*)(g_attn + ((size_t)b * S_LEN + row_lo + 8) * D_MODEL + col) =
                make_float2(to_tf32(O[hd][2] * inv_hi),
                            to_tf32(O[hd][3] * inv_hi));
        }
    }
}

// ---------------------------------------------------------------------------
extern "C" void kernel_launch(void* const* d_in, const int* in_sizes, int n_in,
                              void* d_out, int out_size)
{
    const float* x      = (const float*)d_in[0];
    const int*   pmask  = (const int*)d_in[1];
    const float* w_qkv  = (const float*)d_in[2];
    const float* w_o    = (const float*)d_in[3];
    float*       out    = (float*)d_out;

    cudaFuncSetAttribute(attn_tc,
                         cudaFuncAttributeMaxDynamicSharedMemorySize, ATTN_SM_BYTES);
    cudaFuncSetAttribute(mm_tf32<0>,
                         cudaFuncAttributeMaxDynamicSharedMemorySize, MM_SM_BYTES);
    cudaFuncSetAttribute(mm_tf32<1>,
                         cudaFuncAttributeMaxDynamicSharedMemorySize, MM_SM_BYTES);

    float *xc, *wc, *woc, *attn_ptr;
    cudaGetSymbolAddress((void**)&xc, g_xc);
    cudaGetSymbolAddress((void**)&wc, g_wc);
    cudaGetSymbolAddress((void**)&woc, g_woc);
    cudaGetSymbolAddress((void**)&attn_ptr, g_attn);

    rope_table_kernel<<<(S_LEN * 32 + 255) / 256, 256>>>();
    cvt_all_kernel<<<(N4_X + N4_W + N4_WO + 255) / 256, 256>>>(
        (const float4*)x, (const float4*)w_qkv, (const float4*)w_o);
    bias_kernel<<<(BATCH * S_LEN + 255) / 256, 256>>>(pmask);

    // QKV projection + RoPE (+1/8 q-scale, V transposed): M=8192, N=3072
    mm_tf32<0><<<dim3(3 * D_MODEL / 128, (BATCH * S_LEN) / 128), 256, MM_SM_BYTES>>>(xc, wc, nullptr);
    // Flash attention (tensor cores), q-tile 128 rows
    attn_tc<<<dim3(16, BH), 256, ATTN_SM_BYTES>>>();
    // Output projection: M=8192, N=1024
    mm_tf32<1><<<dim3(D_MODEL / 128, (BATCH * S_LEN) / 128), 256, MM_SM_BYTES>>>(attn_ptr, woc, out);
}